// round 8
// baseline (speedup 1.0000x reference)
#include <cuda_runtime.h>
#include <math.h>

// Problem constants (fixed by the reference)
constexpr int NN  = 100000;
constexpr int NN1 = 60000;
constexpr int NN2 = 30000;
constexpr int EE  = 1600000;
constexpr int DIN = 128;
constexpr int HH  = 64;

// ---------------- float scratch ----------------
constexpr long long F_HMASK = 0;
constexpr long long F_HNEI1 = F_HMASK + (long long)NN * HH;
constexpr long long F_HNEI2 = F_HNEI1 + (long long)NN1 * HH;
constexpr long long F_SUM1  = F_HNEI2 + (long long)NN2 * HH;
constexpr long long F_SUM2  = F_SUM1 + (long long)NN * HH;
constexpr long long F_TOTAL = F_SUM2 + (long long)NN * HH;

__device__ float g_fscratch[F_TOTAL];

// ---------------- int scratch ----------------
constexpr long long I_DEG1 = 0;
constexpr long long I_DEG2 = I_DEG1 + NN;
constexpr long long I_ROW1 = I_DEG2 + NN;
constexpr long long I_ROW2 = I_ROW1 + NN;
constexpr long long I_CUR1 = I_ROW2 + NN;
constexpr long long I_CUR2 = I_CUR1 + NN;
constexpr long long I_CTR  = I_CUR2 + NN;     // 2 counters, padded
constexpr long long I_EDST1 = I_CTR + 32;
constexpr long long I_EDST2 = I_EDST1 + EE;
constexpr long long I_TOTAL = I_EDST2 + EE;

__device__ int g_iscratch[I_TOTAL];

// ---------------- helpers ----------------
__device__ __forceinline__ float elu1(float x) { return x > 0.f ? x : expm1f(x); }
__device__ __forceinline__ float4 elu4(float4 v) {
    v.x = elu1(v.x); v.y = elu1(v.y); v.z = elu1(v.z); v.w = elu1(v.w);
    return v;
}

// ================= input GEMM (proven R3 version): Y = elu(X @ W + b) =================
// 64x64 tile, 256 threads, 4x4 register block per thread. 32KB static smem.
template<int K, bool BIASELU>
__global__ __launch_bounds__(256)
void gemm64_kernel(const float* __restrict__ X, const float* __restrict__ W,
                   const float* __restrict__ b, float* __restrict__ Y, int rows)
{
    constexpr int K4 = K / 4;
    __shared__ float4 Xs[64 * K4];
    __shared__ float4 Wt[64 * K4];

    const int t = threadIdx.x;
    const int rowBase = blockIdx.x * 64;

    const float4* X4 = (const float4*)X;
    for (int idx = t; idx < 64 * K4; idx += 256) {
        int r  = idx / K4;
        int k4 = idx % K4;
        int gr = rowBase + r;
        float4 v = make_float4(0.f, 0.f, 0.f, 0.f);
        if (gr < rows) v = X4[(long long)gr * K4 + k4];
        Xs[idx] = v;
    }
    for (int idx = t; idx < K * 64; idx += 256) {
        int k = idx >> 6;
        int c = idx & 63;
        int k4 = k >> 2, kk = k & 3;
        ((float*)&Wt[c * K4 + (k4 ^ ((c >> 2) & 7))])[kk] = W[idx];
    }
    __syncthreads();

    const int c4  = t & 15;
    const int r0  = (t >> 4) * 4;
    const int swz = c4 & 7;

    float acc[4][4];
#pragma unroll
    for (int i = 0; i < 4; i++)
#pragma unroll
        for (int j = 0; j < 4; j++) acc[i][j] = 0.f;

#pragma unroll 8
    for (int k4 = 0; k4 < K4; k4++) {
        float4 xv[4], wv[4];
#pragma unroll
        for (int i = 0; i < 4; i++) xv[i] = Xs[(r0 + i) * K4 + k4];
#pragma unroll
        for (int j = 0; j < 4; j++) wv[j] = Wt[(c4 * 4 + j) * K4 + (k4 ^ swz)];
#pragma unroll
        for (int i = 0; i < 4; i++)
#pragma unroll
            for (int j = 0; j < 4; j++)
                acc[i][j] += xv[i].x * wv[j].x + xv[i].y * wv[j].y +
                             xv[i].z * wv[j].z + xv[i].w * wv[j].w;
    }

    float4 bias = make_float4(0.f, 0.f, 0.f, 0.f);
    if (BIASELU) bias = ((const float4*)b)[c4];

    float4* Y4 = (float4*)Y;
#pragma unroll
    for (int i = 0; i < 4; i++) {
        int gr = rowBase + r0 + i;
        if (gr < rows) {
            float4 o = make_float4(acc[i][0] + bias.x, acc[i][1] + bias.y,
                                   acc[i][2] + bias.z, acc[i][3] + bias.w);
            if (BIASELU) o = elu4(o);
            Y4[(long long)gr * 16 + c4] = o;
        }
    }
}

// ================= CSR build =================
__global__ __launch_bounds__(256)
void zero_kernel(int* __restrict__ d1, int* __restrict__ d2, int* __restrict__ ctr)
{
    int i = blockIdx.x * 256 + threadIdx.x;
    if (i < NN) { d1[i] = 0; d2[i] = 0; }
    if (i < 2) ctr[i] = 0;
}

__global__ __launch_bounds__(256)
void hist2_kernel(const int* __restrict__ src1, const int* __restrict__ src2,
                  int* __restrict__ deg1, int* __restrict__ deg2)
{
    int e = blockIdx.x * 256 + threadIdx.x;
    if (e < EE)            atomicAdd(deg1 + __ldg(src1 + e), 1);
    else if (e < 2 * EE)   atomicAdd(deg2 + __ldg(src2 + e - EE), 1);
}

__global__ __launch_bounds__(256)
void base2_kernel(const int* __restrict__ deg1, int* __restrict__ row1, int* __restrict__ cur1,
                  const int* __restrict__ deg2, int* __restrict__ row2, int* __restrict__ cur2,
                  int* __restrict__ ctr, int nb)
{
    __shared__ int warpTot[8];
    __shared__ int blockBase;
    int rel = blockIdx.x >= nb;
    const int* deg = rel ? deg2 : deg1;
    int* rowp = rel ? row2 : row1;
    int* cur  = rel ? cur2 : cur1;
    int* counter = ctr + rel;

    int i = (blockIdx.x - rel * nb) * 256 + threadIdx.x;
    int lane = threadIdx.x & 31;
    int wid  = threadIdx.x >> 5;

    int d = (i < NN) ? deg[i] : 0;
    int x = d;
#pragma unroll
    for (int o = 1; o < 32; o <<= 1) {
        int y = __shfl_up_sync(0xffffffffu, x, o);
        if (lane >= o) x += y;
    }
    if (lane == 31) warpTot[wid] = x;
    __syncthreads();
    if (threadIdx.x == 0) {
        int s = 0;
#pragma unroll
        for (int w = 0; w < 8; w++) { int tw = warpTot[w]; warpTot[w] = s; s += tw; }
        blockBase = atomicAdd(counter, s);
    }
    __syncthreads();
    int base = blockBase + warpTot[wid] + x - d;
    if (i < NN) { rowp[i] = base; cur[i] = base; }
}

__global__ __launch_bounds__(256)
void reorder2_kernel(const int* __restrict__ src1, const int* __restrict__ dst1,
                     int* __restrict__ cur1, int* __restrict__ edst1,
                     const int* __restrict__ src2, const int* __restrict__ dst2,
                     int* __restrict__ cur2, int* __restrict__ edst2)
{
    int e = blockIdx.x * 256 + threadIdx.x;
    if (e < EE) {
        int s = __ldg(src1 + e);
        int pos = atomicAdd(cur1 + s, 1);
        edst1[pos] = __ldg(dst1 + e);
    } else if (e < 2 * EE) {
        e -= EE;
        int s = __ldg(src2 + e);
        int pos = atomicAdd(cur2 + s, 1);
        edst2[pos] = __ldg(dst2 + e);
    }
}

// ================= aggregate: one warp per node (proven R3 version) =================
__global__ __launch_bounds__(256)
void agg_kernel(const int* __restrict__ rowptr, const int* __restrict__ deg,
                const int* __restrict__ edst, const float2* __restrict__ hnei,
                float2* __restrict__ sum, int n)
{
    int warp = (blockIdx.x * 256 + threadIdx.x) >> 5;
    int lane = threadIdx.x & 31;
    if (warp >= n) return;

    int base = __ldg(rowptr + warp);
    int d    = __ldg(deg + warp);

    float2 acc = make_float2(0.f, 0.f);
    for (int j0 = 0; j0 < d; j0 += 32) {
        int e = 0;
        if (j0 + lane < d) e = __ldg(edst + base + j0 + lane);
        int m = min(32, d - j0);
        int jj = 0;
        for (; jj + 4 <= m; jj += 4) {
            int d0 = __shfl_sync(0xffffffffu, e, jj);
            int d1 = __shfl_sync(0xffffffffu, e, jj + 1);
            int d2 = __shfl_sync(0xffffffffu, e, jj + 2);
            int d3 = __shfl_sync(0xffffffffu, e, jj + 3);
            float2 v0 = __ldg(hnei + (long long)d0 * 32 + lane);
            float2 v1 = __ldg(hnei + (long long)d1 * 32 + lane);
            float2 v2 = __ldg(hnei + (long long)d2 * 32 + lane);
            float2 v3 = __ldg(hnei + (long long)d3 * 32 + lane);
            acc.x += v0.x + v1.x + v2.x + v3.x;
            acc.y += v0.y + v1.y + v2.y + v3.y;
        }
        for (; jj < m; jj++) {
            int dd = __shfl_sync(0xffffffffu, e, jj);
            float2 v = __ldg(hnei + (long long)dd * 32 + lane);
            acc.x += v.x;
            acc.y += v.y;
        }
    }
    sum[(long long)warp * 32 + lane] = acc;
}

// ================= fused A-GEMM x2 + epilogue (32KB static smem) =================
// acc1 = sum1_tile @ A0 ; acc2 = sum2_tile @ A1  (64x64 tile, 4x4 blocks)
// out0 = elu(htar + acc1/deg1); out1 = elu(hmask + acc1/deg1)
// out2 = elu(htar + acc2/deg2); out3 = elu(hmask + acc2/deg2)
__global__ __launch_bounds__(256)
void gemm_epi_kernel(const float* __restrict__ sum1, const float* __restrict__ A0,
                     const float* __restrict__ sum2, const float* __restrict__ A1,
                     const int* __restrict__ deg1, const int* __restrict__ deg2,
                     const float4* __restrict__ hmask, float* __restrict__ out)
{
    constexpr int K4 = HH / 4;           // 16
    __shared__ float4 Xs[64 * K4];       // 16KB
    __shared__ float4 Wt[64 * K4];       // 16KB

    const int t = threadIdx.x;
    const int rowBase = blockIdx.x * 64;
    const int c4  = t & 15;
    const int r0  = (t >> 4) * 4;
    const int swz = c4 & 7;

    float acc1[4][4], acc2[4][4];

    for (int phase = 0; phase < 2; phase++) {
        const float4* X4 = phase ? (const float4*)sum2 : (const float4*)sum1;
        const float* W   = phase ? A1 : A0;
        if (phase) __syncthreads();      // all reads of phase-0 tiles done

#pragma unroll
        for (int it = 0; it < 4; it++) {
            int idx = t + it * 256;      // [0, 1024)
            int r  = idx >> 4;
            int k4 = idx & 15;
            int gr = rowBase + r;
            float4 v = make_float4(0.f, 0.f, 0.f, 0.f);
            if (gr < NN) v = X4[(long long)gr * K4 + k4];
            Xs[idx] = v;
        }
#pragma unroll
        for (int it = 0; it < 16; it++) {
            int idx = t + it * 256;      // [0, 4096)
            int k = idx >> 6;
            int c = idx & 63;
            ((float*)&Wt[c * K4 + ((k >> 2) ^ ((c >> 2) & 7))])[k & 3] = W[idx];
        }
        __syncthreads();

        float (*acc)[4] = phase ? acc2 : acc1;
#pragma unroll
        for (int i = 0; i < 4; i++)
#pragma unroll
            for (int j = 0; j < 4; j++) acc[i][j] = 0.f;

#pragma unroll 4
        for (int k4 = 0; k4 < K4; k4++) {
            float4 xv[4];
#pragma unroll
            for (int i = 0; i < 4; i++) xv[i] = Xs[(r0 + i) * K4 + k4];
#pragma unroll
            for (int j = 0; j < 4; j++) {
                float4 wv = Wt[(c4 * 4 + j) * K4 + (k4 ^ swz)];
#pragma unroll
                for (int i = 0; i < 4; i++)
                    acc[i][j] += xv[i].x * wv.x + xv[i].y * wv.y +
                                 xv[i].z * wv.z + xv[i].w * wv.w;
            }
        }
    }

    // epilogue
    float4* O = (float4*)out;
    const float4* HT = O + 4LL * NN * 16;
#pragma unroll
    for (int i = 0; i < 4; i++) {
        int gr = rowBase + r0 + i;
        if (gr >= NN) continue;
        int d1 = __ldg(deg1 + gr);
        int d2 = __ldg(deg2 + gr);
        float inv1 = d1 > 0 ? 1.f / (float)d1 : 1.f;
        float inv2 = d2 > 0 ? 1.f / (float)d2 : 1.f;
        float4 a1 = make_float4(acc1[i][0] * inv1, acc1[i][1] * inv1,
                                acc1[i][2] * inv1, acc1[i][3] * inv1);
        float4 a2 = make_float4(acc2[i][0] * inv2, acc2[i][1] * inv2,
                                acc2[i][2] * inv2, acc2[i][3] * inv2);
        long long g = (long long)gr * 16 + c4;
        float4 ht = HT[g];
        float4 hm = hmask[g];
        float4 v;
        v = make_float4(ht.x + a1.x, ht.y + a1.y, ht.z + a1.z, ht.w + a1.w);
        O[0LL * NN * 16 + g] = elu4(v);
        v = make_float4(hm.x + a1.x, hm.y + a1.y, hm.z + a1.z, hm.w + a1.w);
        O[1LL * NN * 16 + g] = elu4(v);
        v = make_float4(ht.x + a2.x, ht.y + a2.y, ht.z + a2.z, ht.w + a2.w);
        O[2LL * NN * 16 + g] = elu4(v);
        v = make_float4(hm.x + a2.x, hm.y + a2.y, hm.z + a2.z, hm.w + a2.w);
        O[3LL * NN * 16 + g] = elu4(v);
    }
}

// ================= launch (single stream, no statics, no attribute calls) =========
extern "C" void kernel_launch(void* const* d_in, const int* in_sizes, int n_in,
                              void* d_out, int out_size)
{
    const float* feats0    = (const float*)d_in[0];
    const float* feats1    = (const float*)d_in[1];
    const float* feats2    = (const float*)d_in[2];
    const float* mask_feat = (const float*)d_in[3];
    const int*   src1      = (const int*)d_in[4];
    const int*   dst1      = (const int*)d_in[5];
    const int*   src2      = (const int*)d_in[6];
    const int*   dst2      = (const int*)d_in[7];
    const float* W0        = (const float*)d_in[8];
    const float* b0        = (const float*)d_in[9];
    const float* W1        = (const float*)d_in[10];
    const float* b1        = (const float*)d_in[11];
    const float* W2        = (const float*)d_in[12];
    const float* b2        = (const float*)d_in[13];
    const float* A0        = (const float*)d_in[14];
    const float* A1        = (const float*)d_in[15];

    float* out = (float*)d_out;

    void* fp = nullptr; cudaGetSymbolAddress(&fp, g_fscratch);
    void* ip = nullptr; cudaGetSymbolAddress(&ip, g_iscratch);
    float* F = (float*)fp;
    int*   I = (int*)ip;

    float* hmask = F + F_HMASK;
    float* hnei1 = F + F_HNEI1;
    float* hnei2 = F + F_HNEI2;
    float* sum1  = F + F_SUM1;
    float* sum2  = F + F_SUM2;

    int* deg1 = I + I_DEG1;
    int* deg2 = I + I_DEG2;
    int* row1 = I + I_ROW1;
    int* row2 = I + I_ROW2;
    int* cur1 = I + I_CUR1;
    int* cur2 = I + I_CUR2;
    int* ctr  = I + I_CTR;
    int* edst1 = I + I_EDST1;
    int* edst2 = I + I_EDST2;

    float* htar = out + 4LL * NN * HH;

    auto cdiv = [](long long a, long long b) { return (int)((a + b - 1) / b); };

    const int NB = cdiv(NN, 256);

    // CSR build chain
    zero_kernel<<<NB, 256>>>(deg1, deg2, ctr);
    hist2_kernel<<<cdiv(2LL * EE, 256), 256>>>(src1, src2, deg1, deg2);
    base2_kernel<<<2 * NB, 256>>>(deg1, row1, cur1, deg2, row2, cur2, ctr, NB);
    reorder2_kernel<<<cdiv(2LL * EE, 256), 256>>>(src1, dst1, cur1, edst1,
                                                  src2, dst2, cur2, edst2);

    // Input GEMMs (+bias +ELU)
    gemm64_kernel<DIN, true><<<cdiv(NN1, 64), 256>>>(feats1,    W1, b1, hnei1, NN1);
    gemm64_kernel<DIN, true><<<cdiv(NN2, 64), 256>>>(feats2,    W2, b2, hnei2, NN2);
    gemm64_kernel<DIN, true><<<cdiv(NN,  64), 256>>>(feats0,    W0, b0, htar,  NN);
    gemm64_kernel<DIN, true><<<cdiv(NN,  64), 256>>>(mask_feat, W0, b0, hmask, NN);

    // Gather-aggregate (writes sum exactly once per row; deg doubles as cnt)
    agg_kernel<<<cdiv((long long)NN * 32, 256), 256>>>(row1, deg1, edst1,
                                                       (const float2*)hnei1, (float2*)sum1, NN);
    agg_kernel<<<cdiv((long long)NN * 32, 256), 256>>>(row2, deg2, edst2,
                                                       (const float2*)hnei2, (float2*)sum2, NN);

    // Fused A-GEMM x2 + epilogue (divide by deg inside; T1/T2 eliminated)
    gemm_epi_kernel<<<cdiv(NN, 64), 256>>>(sum1, A0, sum2, A1, deg1, deg2,
                                           (const float4*)hmask, out);
}